// round 3
// baseline (speedup 1.0000x reference)
#include <cuda_runtime.h>

#define UNITS 512
#define N_DOP 128
#define N_INPUT 512

#define BM 128
#define BN 128
#define BKK 8

__device__ float g_mult[UNITS];

// Replicates np.linspace(1, 511, 128).astype(np.int32):
// y = arange(128) * (510/127); y += 1; endpoint forced to 511; truncate.
__device__ __forceinline__ int dop_index(int j) {
    if (j == N_DOP - 1) return UNITS - 1;
    const double step = 510.0 / 127.0;
    return (int)((double)j * step + 1.0);
}

__global__ void prep_kernel(const float* __restrict__ w,
                            const float* __restrict__ dop_old,
                            const float* __restrict__ indicator,
                            const int* __restrict__ bc_raw) {
    __shared__ float s_mult[UNITS];
    __shared__ float s_fac[N_DOP];
    __shared__ int   s_d[N_DOP];
    __shared__ unsigned char s_act[N_DOP];
    __shared__ unsigned char s_isdop[UNITS];

    const int tid = threadIdx.x;

    for (int c = tid; c < UNITS; c += blockDim.x) { s_mult[c] = 1.0f; s_isdop[c] = 0; }
    __syncthreads();
    if (tid < N_DOP) s_isdop[dop_index(tid)] = 1;

    // batch_ctr: decode int32 or float32 bits defensively
    float bc;
    {
        int iv = bc_raw[0];
        if (iv >= -1000000 && iv <= 1000000) bc = (float)iv;
        else bc = __int_as_float(iv);
    }

    const int wid = tid >> 5, lane = tid & 31;
    const int nwarps = blockDim.x >> 5;
    for (int j = wid; j < N_DOP; j += nwarps) {
        const int d = dop_index(j);
        float s = 0.0f;
        for (int i = lane; i < N_INPUT; i += 32)
            s += fabsf(w[i * UNITS + d] - dop_old[i * UNITS + d]);
        #pragma unroll
        for (int o = 16; o > 0; o >>= 1) s += __shfl_xor_sync(0xffffffffu, s, o);
        if (lane == 0) {
            const float diff = s * (1.0f / (float)N_INPUT);
            s_fac[j] = 1.0f + 10.0f * diff;
            s_d[j]   = d;
            s_act[j] = (diff > 0.0f) && ((bc - indicator[j]) > 2.0f);
        }
    }
    __syncthreads();

    // Phase 1: left factors (targets d-1, unique among themselves)
    if (tid < N_DOP) {
        const int d = s_d[tid];
        const int c = d - 1;  // d >= 1 always
        const bool leftok = !s_isdop[c];
        if (s_act[tid] && leftok) s_mult[c] *= s_fac[tid];
    }
    __syncthreads();

    // Phase 2: right factors (col 0 may ALSO receive d=511's right factor -> multiplicative)
    if (tid < N_DOP) {
        const int d = s_d[tid];
        const int c = (d + 1) & (UNITS - 1);
        const bool rightok = (d + 1 >= UNITS) ? true : (!s_isdop[d + 1]);
        if (s_act[tid] && rightok) s_mult[c] *= s_fac[tid];
    }
    __syncthreads();

    for (int c = tid; c < UNITS; c += blockDim.x) g_mult[c] = s_mult[c];
}

// C[M,512] = relu(A[M,512] @ (W[512,512] * mult[col]) + bias[col])
// 128x128 block tile, 8x8 per-thread tile, double-buffered smem.
__global__ __launch_bounds__(256, 2)
void gemm_kernel(const float* __restrict__ A, const float* __restrict__ W,
                 const float* __restrict__ bias, float* __restrict__ C) {
    __shared__ float As[2][BKK][BM];
    __shared__ float Bs[2][BKK][BN];

    const int tid = threadIdx.x;
    const int bx = blockIdx.x;   // N tile
    const int by = blockIdx.y;   // M tile
    const int tx = tid & 15;
    const int ty = tid >> 4;

    // A tile loader: 128 rows x 8 cols, one float4/thread
    const int arow = tid >> 1;
    const int acol = (tid & 1) << 2;
    // B tile loader: 8 rows x 128 cols, one float4/thread
    const int brow = tid >> 5;
    const int bcol = (tid & 31) << 2;

    const float* Ap = A + (size_t)(by * BM + arow) * N_INPUT + acol;
    const float* Bp = W + (size_t)brow * UNITS + bx * BN + bcol;

    const float4 msc = *(const float4*)&g_mult[bx * BN + bcol];

    float acc[8][8];
    #pragma unroll
    for (int i = 0; i < 8; i++)
        #pragma unroll
        for (int j = 0; j < 8; j++) acc[i][j] = 0.0f;

    // Preload tile 0 into buffer 0
    {
        float4 a  = *(const float4*)(Ap);
        float4 bv = *(const float4*)(Bp);
        As[0][acol + 0][arow] = a.x;
        As[0][acol + 1][arow] = a.y;
        As[0][acol + 2][arow] = a.z;
        As[0][acol + 3][arow] = a.w;
        bv.x *= msc.x; bv.y *= msc.y; bv.z *= msc.z; bv.w *= msc.w;
        *(float4*)&Bs[0][brow][bcol] = bv;
    }
    __syncthreads();

    int buf = 0;
    for (int k0 = 0; k0 < N_INPUT; k0 += BKK) {
        const int knext = k0 + BKK;
        float4 a_n, b_n;
        if (knext < N_INPUT) {
            a_n = *(const float4*)(Ap + knext);
            b_n = *(const float4*)(Bp + (size_t)knext * UNITS);
        }

        #pragma unroll
        for (int k = 0; k < BKK; k++) {
            float ra[8], rb[8];
            *(float4*)(ra)     = *(const float4*)&As[buf][k][ty * 8];
            *(float4*)(ra + 4) = *(const float4*)&As[buf][k][ty * 8 + 4];
            *(float4*)(rb)     = *(const float4*)&Bs[buf][k][tx * 8];
            *(float4*)(rb + 4) = *(const float4*)&Bs[buf][k][tx * 8 + 4];
            #pragma unroll
            for (int i = 0; i < 8; i++)
                #pragma unroll
                for (int j = 0; j < 8; j++)
                    acc[i][j] = fmaf(ra[i], rb[j], acc[i][j]);
        }

        if (knext < N_INPUT) {
            const int nb = buf ^ 1;
            As[nb][acol + 0][arow] = a_n.x;
            As[nb][acol + 1][arow] = a_n.y;
            As[nb][acol + 2][arow] = a_n.z;
            As[nb][acol + 3][arow] = a_n.w;
            b_n.x *= msc.x; b_n.y *= msc.y; b_n.z *= msc.z; b_n.w *= msc.w;
            *(float4*)&Bs[nb][brow][bcol] = b_n;
            __syncthreads();
            buf = nb;
        }
    }

    const int row0 = by * BM + ty * 8;
    const int col0 = bx * BN + tx * 8;
    float bb[8];
    *(float4*)(bb)     = *(const float4*)&bias[col0];
    *(float4*)(bb + 4) = *(const float4*)&bias[col0 + 4];

    #pragma unroll
    for (int i = 0; i < 8; i++) {
        float4 o0, o1;
        o0.x = fmaxf(acc[i][0] + bb[0], 0.0f);
        o0.y = fmaxf(acc[i][1] + bb[1], 0.0f);
        o0.z = fmaxf(acc[i][2] + bb[2], 0.0f);
        o0.w = fmaxf(acc[i][3] + bb[3], 0.0f);
        o1.x = fmaxf(acc[i][4] + bb[4], 0.0f);
        o1.y = fmaxf(acc[i][5] + bb[5], 0.0f);
        o1.z = fmaxf(acc[i][6] + bb[6], 0.0f);
        o1.w = fmaxf(acc[i][7] + bb[7], 0.0f);
        float* cp = C + (size_t)(row0 + i) * UNITS + col0;
        *(float4*)(cp)     = o0;
        *(float4*)(cp + 4) = o1;
    }
}

extern "C" void kernel_launch(void* const* d_in, const int* in_sizes, int n_in,
                              void* d_out, int out_size) {
    const float* x   = (const float*)d_in[0];
    const float* w   = (const float*)d_in[1];
    const float* b   = (const float*)d_in[2];
    const float* old = (const float*)d_in[3];
    const float* ind = (const float*)d_in[4];
    const int*   bc  = (const int*)d_in[5];

    const int M = in_sizes[0] / N_INPUT;

    prep_kernel<<<1, 1024>>>(w, old, ind, bc);

    dim3 grid(UNITS / BN, M / BM);
    gemm_kernel<<<grid, 256>>>(x, w, b, (float*)d_out);
}

// round 8
// speedup vs baseline: 1.9802x; 1.9802x over previous
#include <cuda_runtime.h>
#include <cuda_bf16.h>
#include <cstdint>

#define UNITS 512
#define N_DOP 128
#define N_INPUT 512

#define BM 128
#define BN 128
#define BK 32
#define THREADS 512
#define KSTAGES (N_INPUT / BK)   // 16

// dynamic smem: double buffer of {Ahi 8K | Alo 8K | Bhi 8K | Blo 8K}
#define BUF_STRIDE 32768
#define OFF_AHI 0
#define OFF_ALO 8192
#define OFF_BHI 16384
#define OFF_BLO 24576
#define SMEM_DYN (2 * BUF_STRIDE + 128)

__device__ float g_mult[UNITS];
__device__ __nv_bfloat16 g_whi[UNITS * N_INPUT];  // [n][k]
__device__ __nv_bfloat16 g_wlo[UNITS * N_INPUT];

__device__ __forceinline__ uint32_t smem_u32(const void* p) {
    uint32_t a;
    asm("{ .reg .u64 t; cvta.to.shared.u64 t, %1; cvt.u32.u64 %0, t; }" : "=r"(a) : "l"(p));
    return a;
}
// 64-byte rows (32 bf16), 16B chunks; conflict-free for ldmatrix & STS
__device__ __forceinline__ uint32_t swz(int row, int chunk) {
    return (uint32_t)(row * 64 + ((chunk ^ ((row >> 1) & 3)) << 4));
}
__device__ __forceinline__ void ldsm4(uint32_t* r, uint32_t addr) {
    asm volatile("ldmatrix.sync.aligned.m8n8.x4.shared.b16 {%0,%1,%2,%3}, [%4];"
                 : "=r"(r[0]), "=r"(r[1]), "=r"(r[2]), "=r"(r[3]) : "r"(addr));
}
__device__ __forceinline__ void ldsm2(uint32_t* r, uint32_t addr) {
    asm volatile("ldmatrix.sync.aligned.m8n8.x2.shared.b16 {%0,%1}, [%2];"
                 : "=r"(r[0]), "=r"(r[1]) : "r"(addr));
}
__device__ __forceinline__ void cp16(uint32_t dst, const void* src) {
    asm volatile("cp.async.cg.shared.global [%0], [%1], 16;" :: "r"(dst), "l"(src));
}
__device__ __forceinline__ void mma_bf16(float* c, const uint32_t* a, const uint32_t* b) {
    asm volatile(
        "mma.sync.aligned.m16n8k16.row.col.f32.bf16.bf16.f32 "
        "{%0,%1,%2,%3}, {%4,%5,%6,%7}, {%8,%9}, {%0,%1,%2,%3};"
        : "+f"(c[0]), "+f"(c[1]), "+f"(c[2]), "+f"(c[3])
        : "r"(a[0]), "r"(a[1]), "r"(a[2]), "r"(a[3]), "r"(b[0]), "r"(b[1]));
}
__device__ __forceinline__ uint32_t pack2(float a, float b) {
    return (uint32_t)__bfloat16_as_ushort(__float2bfloat16(a)) |
           ((uint32_t)__bfloat16_as_ushort(__float2bfloat16(b)) << 16);
}

// ---------------------------------------------------------------------------
// prep: column multipliers (validated in R3, rel_err 1.1e-7)
// ---------------------------------------------------------------------------
__device__ __forceinline__ int dop_index(int j) {
    if (j == N_DOP - 1) return UNITS - 1;
    const double step = 510.0 / 127.0;
    return (int)((double)j * step + 1.0);
}

__global__ void prep_kernel(const float* __restrict__ w,
                            const float* __restrict__ dop_old,
                            const float* __restrict__ indicator,
                            const int* __restrict__ bc_raw) {
    __shared__ float s_mult[UNITS];
    __shared__ float s_fac[N_DOP];
    __shared__ int   s_d[N_DOP];
    __shared__ unsigned char s_act[N_DOP];
    __shared__ unsigned char s_isdop[UNITS];

    const int tid = threadIdx.x;
    for (int c = tid; c < UNITS; c += blockDim.x) { s_mult[c] = 1.0f; s_isdop[c] = 0; }
    __syncthreads();
    if (tid < N_DOP) s_isdop[dop_index(tid)] = 1;

    float bc;
    {
        int iv = bc_raw[0];
        if (iv >= -1000000 && iv <= 1000000) bc = (float)iv;
        else bc = __int_as_float(iv);
    }

    const int wid = tid >> 5, lane = tid & 31;
    const int nwarps = blockDim.x >> 5;
    for (int j = wid; j < N_DOP; j += nwarps) {
        const int d = dop_index(j);
        float s = 0.0f;
        for (int i = lane; i < N_INPUT; i += 32)
            s += fabsf(w[i * UNITS + d] - dop_old[i * UNITS + d]);
        #pragma unroll
        for (int o = 16; o > 0; o >>= 1) s += __shfl_xor_sync(0xffffffffu, s, o);
        if (lane == 0) {
            const float diff = s * (1.0f / (float)N_INPUT);
            s_fac[j] = 1.0f + 10.0f * diff;
            s_d[j]   = d;
            s_act[j] = (diff > 0.0f) && ((bc - indicator[j]) > 2.0f);
        }
    }
    __syncthreads();

    if (tid < N_DOP) {
        const int d = s_d[tid];
        const int c = d - 1;
        if (s_act[tid] && !s_isdop[c]) s_mult[c] *= s_fac[tid];
    }
    __syncthreads();
    if (tid < N_DOP) {
        const int d = s_d[tid];
        const int c = (d + 1) & (UNITS - 1);
        const bool rightok = (d + 1 >= UNITS) ? true : (!s_isdop[d + 1]);
        if (s_act[tid] && rightok) s_mult[c] *= s_fac[tid];
    }
    __syncthreads();
    for (int c = tid; c < UNITS; c += blockDim.x) g_mult[c] = s_mult[c];
}

// ---------------------------------------------------------------------------
// prep2: split W*mult into bf16 hi/lo, transposed to [n][k]
// ---------------------------------------------------------------------------
__global__ void prep2_kernel(const float* __restrict__ w) {
    const int idx = blockIdx.x * blockDim.x + threadIdx.x;
    const int n = idx >> 9;
    const int k = idx & (N_INPUT - 1);
    const float we = w[k * UNITS + n] * g_mult[n];
    const __nv_bfloat16 hi = __float2bfloat16(we);
    const __nv_bfloat16 lo = __float2bfloat16(we - __bfloat162float(hi));
    g_whi[idx] = hi;
    g_wlo[idx] = lo;
}

// ---------------------------------------------------------------------------
// GEMM: relu(X @ (W*mult) + b) via 3xBF16-split mma.sync, double-buffered
// ---------------------------------------------------------------------------
__global__ __launch_bounds__(THREADS, 1)
void gemm_kernel(const float* __restrict__ X, const float* __restrict__ bias,
                 float* __restrict__ C) {
    extern __shared__ char dsm[];
    __shared__ float sbias[BN];

    const int tid = threadIdx.x, lane = tid & 31, wid = tid >> 5;
    const int bx = blockIdx.x, by = blockIdx.y;
    const uint32_t raw = smem_u32(dsm);
    const uint32_t base = (raw + 127u) & ~127u;
    char* smp = dsm + (base - raw);

    if (tid < BN) sbias[tid] = bias[bx * BN + tid];

    const int warp_m = wid & 3;      // 4 warps in M
    const int warp_n = wid >> 2;     // 4 warps in N

    // loader: one 16B chunk per thread per matrix (row 0..127, chunk 0..3)
    const int lrow = tid >> 2, lkc = tid & 3;
    const uint32_t sts = swz(lrow, lkc);
    const float* gA = X + ((size_t)by * BM + lrow) * N_INPUT + lkc * 8;
    const __nv_bfloat16* gBh = g_whi + ((size_t)bx * BN + lrow) * N_INPUT + lkc * 8;
    const __nv_bfloat16* gBl = g_wlo + ((size_t)bx * BN + lrow) * N_INPUT + lkc * 8;

    float acc[2][4][4];
    #pragma unroll
    for (int mt = 0; mt < 2; mt++)
        #pragma unroll
        for (int nt = 0; nt < 4; nt++)
            #pragma unroll
            for (int q = 0; q < 4; q++) acc[mt][nt][q] = 0.0f;

    // ---- prologue: stage 0 into buffer 0 ----
    {
        cp16(base + OFF_BHI + sts, gBh);
        cp16(base + OFF_BLO + sts, gBl);
        asm volatile("cp.async.commit_group;" ::: "memory");
        const float4 v0 = *(const float4*)gA;
        const float4 v1 = *(const float4*)(gA + 4);
        const float f[8] = {v0.x, v0.y, v0.z, v0.w, v1.x, v1.y, v1.z, v1.w};
        uint32_t hh[4], ll[4];
        #pragma unroll
        for (int j = 0; j < 4; j++) {
            const float a = f[2 * j], b = f[2 * j + 1];
            hh[j] = pack2(a, b);
            const float ra = a - __bfloat162float(__float2bfloat16(a));
            const float rb = b - __bfloat162float(__float2bfloat16(b));
            ll[j] = pack2(ra, rb);
        }
        *(uint4*)(smp + OFF_AHI + sts) = make_uint4(hh[0], hh[1], hh[2], hh[3]);
        *(uint4*)(smp + OFF_ALO + sts) = make_uint4(ll[0], ll[1], ll[2], ll[3]);
        asm volatile("cp.async.wait_group 0;" ::: "memory");
        __syncthreads();
    }

    uint32_t buf = 0;
    for (int s = 0; s < KSTAGES; s++) {
        const uint32_t cb = base + buf;
        const uint32_t nbuf = buf ^ BUF_STRIDE;
        const bool pf = (s + 1 < KSTAGES);
        float4 v0, v1;
        if (pf) {
            const int ko = (s + 1) * BK;
            cp16(base + nbuf + OFF_BHI + sts, gBh + ko);
            cp16(base + nbuf + OFF_BLO + sts, gBl + ko);
            asm volatile("cp.async.commit_group;" ::: "memory");
            v0 = *(const float4*)(gA + ko);
            v1 = *(const float4*)(gA + ko + 4);
        }

        #pragma unroll
        for (int ks = 0; ks < 2; ks++) {
            uint32_t ah[2][4], al[2][4], bh[4][2], bl[4][2];
            #pragma unroll
            for (int mt = 0; mt < 2; mt++) {
                const int row = warp_m * 32 + mt * 16 + (lane & 15);
                const int ch  = ks * 2 + (lane >> 4);
                const uint32_t o = swz(row, ch);
                ldsm4(ah[mt], cb + OFF_AHI + o);
                ldsm4(al[mt], cb + OFF_ALO + o);
            }
            #pragma unroll
            for (int nt = 0; nt < 4; nt++) {
                const int row = warp_n * 32 + nt * 8 + (lane & 7);
                const int ch  = ks * 2 + ((lane >> 3) & 1);
                const uint32_t o = swz(row, ch);
                ldsm2(bh[nt], cb + OFF_BHI + o);
                ldsm2(bl[nt], cb + OFF_BLO + o);
            }
            #pragma unroll
            for (int mt = 0; mt < 2; mt++)
                #pragma unroll
                for (int nt = 0; nt < 4; nt++) {
                    mma_bf16(acc[mt][nt], ah[mt], bh[nt]);  // xh*wh
                    mma_bf16(acc[mt][nt], ah[mt], bl[nt]);  // xh*wl
                    mma_bf16(acc[mt][nt], al[mt], bh[nt]);  // xl*wh
                }
        }

        if (pf) {
            const float f[8] = {v0.x, v0.y, v0.z, v0.w, v1.x, v1.y, v1.z, v1.w};
            uint32_t hh[4], ll[4];
            #pragma unroll
            for (int j = 0; j < 4; j++) {
                const float a = f[2 * j], b = f[2 * j + 1];
                hh[j] = pack2(a, b);
                const float ra = a - __bfloat162float(__float2bfloat16(a));
                const float rb = b - __bfloat162float(__float2bfloat16(b));
                ll[j] = pack2(ra, rb);
            }
            *(uint4*)(smp + nbuf + OFF_AHI + sts) = make_uint4(hh[0], hh[1], hh[2], hh[3]);
            *(uint4*)(smp + nbuf + OFF_ALO + sts) = make_uint4(ll[0], ll[1], ll[2], ll[3]);
            asm volatile("cp.async.wait_group 0;" ::: "memory");
        }
        __syncthreads();
        buf = nbuf;
    }

    // ---- epilogue: bias + relu, float2 stores ----
    const int gq = lane >> 2, tq = lane & 3;
    #pragma unroll
    for (int mt = 0; mt < 2; mt++) {
        const int r0 = warp_m * 32 + mt * 16 + gq;
        float* crow0 = C + ((size_t)by * BM + r0) * UNITS + bx * BN;
        float* crow1 = crow0 + 8 * UNITS;
        #pragma unroll
        for (int nt = 0; nt < 4; nt++) {
            const int col = warp_n * 32 + nt * 8 + tq * 2;
            float2 o0, o1;
            o0.x = fmaxf(acc[mt][nt][0] + sbias[col], 0.0f);
            o0.y = fmaxf(acc[mt][nt][1] + sbias[col + 1], 0.0f);
            o1.x = fmaxf(acc[mt][nt][2] + sbias[col], 0.0f);
            o1.y = fmaxf(acc[mt][nt][3] + sbias[col + 1], 0.0f);
            *(float2*)(crow0 + col) = o0;
            *(float2*)(crow1 + col) = o1;
        }
    }
}

extern "C" void kernel_launch(void* const* d_in, const int* in_sizes, int n_in,
                              void* d_out, int out_size) {
    const float* x   = (const float*)d_in[0];
    const float* w   = (const float*)d_in[1];
    const float* b   = (const float*)d_in[2];
    const float* old = (const float*)d_in[3];
    const float* ind = (const float*)d_in[4];
    const int*   bc  = (const int*)d_in[5];

    const int M = in_sizes[0] / N_INPUT;

    cudaFuncSetAttribute(gemm_kernel, cudaFuncAttributeMaxDynamicSharedMemorySize, SMEM_DYN);

    prep_kernel<<<1, 1024>>>(w, old, ind, bc);
    prep2_kernel<<<(UNITS * N_INPUT) / 256, 256>>>(w);
    dim3 grid(UNITS / BN, M / BM);
    gemm_kernel<<<grid, THREADS, SMEM_DYN>>>(x, b, (float*)d_out);
}

// round 9
// speedup vs baseline: 4.3629x; 2.2033x over previous
#include <cuda_runtime.h>
#include <cuda_fp16.h>
#include <cstdint>

#define UNITS 512
#define N_DOP 128
#define N_INPUT 512

#define BM 128
#define BN 128
#define BK 32
#define THREADS 512
#define KSTAGES (N_INPUT / BK)   // 16

// dynamic smem: double buffer of {A 8K | B 8K}
#define BUF_STRIDE 16384
#define OFF_A 0
#define OFF_B 8192
#define SMEM_DYN (2 * BUF_STRIDE + 128)

__device__ float g_mult[UNITS];
__device__ float g_fac[N_DOP];
__device__ int   g_act[N_DOP];
__device__ __half g_w16[UNITS * N_INPUT];  // [n][k] = w[k][n] * mult[n]

__device__ __forceinline__ uint32_t smem_u32(const void* p) {
    uint32_t a;
    asm("{ .reg .u64 t; cvta.to.shared.u64 t, %1; cvt.u32.u64 %0, t; }" : "=r"(a) : "l"(p));
    return a;
}
// 64-byte rows (32 fp16), 16B chunks; conflict-free for ldmatrix & STS (verified R8)
__device__ __forceinline__ uint32_t swz(int row, int chunk) {
    return (uint32_t)(row * 64 + ((chunk ^ ((row >> 1) & 3)) << 4));
}
__device__ __forceinline__ void ldsm4(uint32_t* r, uint32_t addr) {
    asm volatile("ldmatrix.sync.aligned.m8n8.x4.shared.b16 {%0,%1,%2,%3}, [%4];"
                 : "=r"(r[0]), "=r"(r[1]), "=r"(r[2]), "=r"(r[3]) : "r"(addr));
}
__device__ __forceinline__ void ldsm2(uint32_t* r, uint32_t addr) {
    asm volatile("ldmatrix.sync.aligned.m8n8.x2.shared.b16 {%0,%1}, [%2];"
                 : "=r"(r[0]), "=r"(r[1]) : "r"(addr));
}
__device__ __forceinline__ void cp16(uint32_t dst, const void* src) {
    asm volatile("cp.async.cg.shared.global [%0], [%1], 16;" :: "r"(dst), "l"(src));
}
__device__ __forceinline__ void mma_fp16(float* c, const uint32_t* a, const uint32_t* b) {
    asm volatile(
        "mma.sync.aligned.m16n8k16.row.col.f32.f16.f16.f32 "
        "{%0,%1,%2,%3}, {%4,%5,%6,%7}, {%8,%9}, {%0,%1,%2,%3};"
        : "+f"(c[0]), "+f"(c[1]), "+f"(c[2]), "+f"(c[3])
        : "r"(a[0]), "r"(a[1]), "r"(a[2]), "r"(a[3]), "r"(b[0]), "r"(b[1]));
}
__device__ __forceinline__ uint32_t pack2h(float a, float b) {
    const __half2 h = __floats2half2_rn(a, b);
    return *(const uint32_t*)&h;
}

__device__ __forceinline__ int dop_index(int j) {
    if (j == N_DOP - 1) return UNITS - 1;
    const double step = 510.0 / 127.0;
    return (int)((double)j * step + 1.0);
}

// ---------------------------------------------------------------------------
// prep_a: 128 blocks, one per dop neuron — per-column |w - old| sum
// ---------------------------------------------------------------------------
__global__ void prep_a_kernel(const float* __restrict__ w,
                              const float* __restrict__ dop_old,
                              const float* __restrict__ indicator,
                              const int* __restrict__ bc_raw) {
    __shared__ float red[8];
    const int j = blockIdx.x;
    const int d = dop_index(j);
    const int tid = threadIdx.x, lane = tid & 31, wid = tid >> 5;

    float s = 0.0f;
    for (int i = tid; i < N_INPUT; i += blockDim.x)
        s += fabsf(w[i * UNITS + d] - dop_old[i * UNITS + d]);
    #pragma unroll
    for (int o = 16; o > 0; o >>= 1) s += __shfl_xor_sync(0xffffffffu, s, o);
    if (lane == 0) red[wid] = s;
    __syncthreads();
    if (tid == 0) {
        float t = 0.0f;
        #pragma unroll
        for (int q = 0; q < 8; q++) t += red[q];
        float bc;
        {
            int iv = bc_raw[0];
            if (iv >= -1000000 && iv <= 1000000) bc = (float)iv;
            else bc = __int_as_float(iv);
        }
        const float diff = t * (1.0f / (float)N_INPUT);
        g_fac[j] = 1.0f + 10.0f * diff;
        g_act[j] = (diff > 0.0f) && ((bc - indicator[j]) > 2.0f);
    }
}

// ---------------------------------------------------------------------------
// prep_b: 1 block — build g_mult (two-phase, handles col-0 collision; R3-validated logic)
// ---------------------------------------------------------------------------
__global__ void prep_b_kernel() {
    __shared__ float s_mult[UNITS];
    __shared__ unsigned char s_isdop[UNITS];
    const int tid = threadIdx.x;
    s_mult[tid] = 1.0f;
    s_isdop[tid] = 0;
    __syncthreads();
    if (tid < N_DOP) s_isdop[dop_index(tid)] = 1;
    __syncthreads();
    if (tid < N_DOP) {
        const int d = dop_index(tid);
        const int c = d - 1;
        if (g_act[tid] && !s_isdop[c]) s_mult[c] *= g_fac[tid];
    }
    __syncthreads();
    if (tid < N_DOP) {
        const int d = dop_index(tid);
        const int c = (d + 1) & (UNITS - 1);
        const bool rightok = (d + 1 >= UNITS) ? true : (!s_isdop[d + 1]);
        if (g_act[tid] && rightok) s_mult[c] *= g_fac[tid];
    }
    __syncthreads();
    g_mult[tid] = s_mult[tid];
}

// ---------------------------------------------------------------------------
// prep2: coalesced transpose+scale+fp16: g_w16[n][k] = fp16(w[k][n]*mult[n])
// ---------------------------------------------------------------------------
__global__ void prep2_kernel(const float* __restrict__ w) {
    __shared__ float tile[32][33];
    const int tx = threadIdx.x, ty = threadIdx.y;
    const int n0 = blockIdx.x * 32, k0 = blockIdx.y * 32;
    tile[ty][tx] = w[(size_t)(k0 + ty) * UNITS + n0 + tx];
    __syncthreads();
    const float m = g_mult[n0 + ty];
    g_w16[(size_t)(n0 + ty) * N_INPUT + k0 + tx] = __float2half_rn(tile[tx][ty] * m);
}

// ---------------------------------------------------------------------------
// GEMM: relu(X @ (W*mult) + b), single-pass fp16 mma.sync, double-buffered
// ---------------------------------------------------------------------------
__global__ __launch_bounds__(THREADS, 1)
void gemm_kernel(const float* __restrict__ X, const float* __restrict__ bias,
                 float* __restrict__ C) {
    extern __shared__ char dsm[];
    __shared__ float sbias[BN];

    const int tid = threadIdx.x, lane = tid & 31, wid = tid >> 5;
    const int bx = blockIdx.x, by = blockIdx.y;
    const uint32_t raw = smem_u32(dsm);
    const uint32_t base = (raw + 127u) & ~127u;
    char* smp = dsm + (base - raw);

    if (tid < BN) sbias[tid] = bias[bx * BN + tid];

    const int warp_m = wid & 3;      // 4 warps in M
    const int warp_n = wid >> 2;     // 4 warps in N

    // loader: one 16B chunk per thread per matrix (row 0..127, chunk 0..3)
    const int lrow = tid >> 2, lkc = tid & 3;
    const uint32_t sts = swz(lrow, lkc);
    const float* gA = X + ((size_t)by * BM + lrow) * N_INPUT + lkc * 8;
    const __half* gB = g_w16 + ((size_t)bx * BN + lrow) * N_INPUT + lkc * 8;

    float acc[2][4][4];
    #pragma unroll
    for (int mt = 0; mt < 2; mt++)
        #pragma unroll
        for (int nt = 0; nt < 4; nt++)
            #pragma unroll
            for (int q = 0; q < 4; q++) acc[mt][nt][q] = 0.0f;

    // ---- prologue: stage 0 into buffer 0 ----
    {
        cp16(base + OFF_B + sts, gB);
        asm volatile("cp.async.commit_group;" ::: "memory");
        const float4 v0 = *(const float4*)gA;
        const float4 v1 = *(const float4*)(gA + 4);
        *(uint4*)(smp + OFF_A + sts) = make_uint4(
            pack2h(v0.x, v0.y), pack2h(v0.z, v0.w),
            pack2h(v1.x, v1.y), pack2h(v1.z, v1.w));
        asm volatile("cp.async.wait_group 0;" ::: "memory");
        __syncthreads();
    }

    uint32_t buf = 0;
    for (int s = 0; s < KSTAGES; s++) {
        const uint32_t cb = base + buf;
        const uint32_t nbuf = buf ^ BUF_STRIDE;
        const bool pf = (s + 1 < KSTAGES);
        float4 v0, v1;
        if (pf) {
            const int ko = (s + 1) * BK;
            cp16(base + nbuf + OFF_B + sts, gB + ko);
            asm volatile("cp.async.commit_group;" ::: "memory");
            v0 = *(const float4*)(gA + ko);
            v1 = *(const float4*)(gA + ko + 4);
        }

        #pragma unroll
        for (int ks = 0; ks < 2; ks++) {
            uint32_t ah[2][4], bh[4][2];
            #pragma unroll
            for (int mt = 0; mt < 2; mt++) {
                const int row = warp_m * 32 + mt * 16 + (lane & 15);
                const int ch  = ks * 2 + (lane >> 4);
                ldsm4(ah[mt], cb + OFF_A + swz(row, ch));
            }
            #pragma unroll
            for (int nt = 0; nt < 4; nt++) {
                const int row = warp_n * 32 + nt * 8 + (lane & 7);
                const int ch  = ks * 2 + ((lane >> 3) & 1);
                ldsm2(bh[nt], cb + OFF_B + swz(row, ch));
            }
            #pragma unroll
            for (int mt = 0; mt < 2; mt++)
                #pragma unroll
                for (int nt = 0; nt < 4; nt++)
                    mma_fp16(acc[mt][nt], ah[mt], bh[nt]);
        }

        if (pf) {
            *(uint4*)(smp + nbuf + OFF_A + sts) = make_uint4(
                pack2h(v0.x, v0.y), pack2h(v0.z, v0.w),
                pack2h(v1.x, v1.y), pack2h(v1.z, v1.w));
            asm volatile("cp.async.wait_group 0;" ::: "memory");
        }
        __syncthreads();
        buf = nbuf;
    }

    // ---- epilogue: bias + relu, float2 stores ----
    const int gq = lane >> 2, tq = lane & 3;
    #pragma unroll
    for (int mt = 0; mt < 2; mt++) {
        const int r0 = warp_m * 32 + mt * 16 + gq;
        float* crow0 = C + ((size_t)by * BM + r0) * UNITS + bx * BN;
        float* crow1 = crow0 + 8 * UNITS;
        #pragma unroll
        for (int nt = 0; nt < 4; nt++) {
            const int col = warp_n * 32 + nt * 8 + tq * 2;
            float2 o0, o1;
            o0.x = fmaxf(acc[mt][nt][0] + sbias[col], 0.0f);
            o0.y = fmaxf(acc[mt][nt][1] + sbias[col + 1], 0.0f);
            o1.x = fmaxf(acc[mt][nt][2] + sbias[col], 0.0f);
            o1.y = fmaxf(acc[mt][nt][3] + sbias[col + 1], 0.0f);
            *(float2*)(crow0 + col) = o0;
            *(float2*)(crow1 + col) = o1;
        }
    }
}

extern "C" void kernel_launch(void* const* d_in, const int* in_sizes, int n_in,
                              void* d_out, int out_size) {
    const float* x   = (const float*)d_in[0];
    const float* w   = (const float*)d_in[1];
    const float* b   = (const float*)d_in[2];
    const float* old = (const float*)d_in[3];
    const float* ind = (const float*)d_in[4];
    const int*   bc  = (const int*)d_in[5];

    const int M = in_sizes[0] / N_INPUT;

    cudaFuncSetAttribute(gemm_kernel, cudaFuncAttributeMaxDynamicSharedMemorySize, SMEM_DYN);

    prep_a_kernel<<<N_DOP, 256>>>(w, old, ind, bc);
    prep_b_kernel<<<1, UNITS>>>();
    dim3 tgrid(UNITS / 32, N_INPUT / 32);
    prep2_kernel<<<tgrid, dim3(32, 32)>>>(w);
    dim3 grid(UNITS / BN, M / BM);
    gemm_kernel<<<grid, THREADS, SMEM_DYN>>>(x, b, (float*)d_out);
}

// round 10
// speedup vs baseline: 5.8765x; 1.3469x over previous
#include <cuda_runtime.h>
#include <cuda_fp16.h>
#include <cstdint>

#define UNITS 512
#define N_DOP 128
#define N_INPUT 512

#define BM 128
#define BN 128
#define BK 32
#define THREADS 256
#define KSTAGES (N_INPUT / BK)   // 16

// dynamic smem: double buffer of {A 8K | B 8K}
#define BUF_STRIDE 16384
#define OFF_A 0
#define OFF_B 8192
#define SMEM_DYN (2 * BUF_STRIDE + 128)

__device__ float g_mult[UNITS];
__device__ float g_fac[N_DOP];
__device__ int   g_act[N_DOP];
__device__ __half g_w16[UNITS * N_INPUT];  // [n][k] = w[k][n] * mult[n]

__device__ __forceinline__ uint32_t smem_u32(const void* p) {
    uint32_t a;
    asm("{ .reg .u64 t; cvta.to.shared.u64 t, %1; cvt.u32.u64 %0, t; }" : "=r"(a) : "l"(p));
    return a;
}
// 64-byte rows (32 fp16), 16B chunks; conflict-free for ldmatrix & STS (verified R8/R9)
__device__ __forceinline__ uint32_t swz(int row, int chunk) {
    return (uint32_t)(row * 64 + ((chunk ^ ((row >> 1) & 3)) << 4));
}
__device__ __forceinline__ void ldsm4(uint32_t* r, uint32_t addr) {
    asm volatile("ldmatrix.sync.aligned.m8n8.x4.shared.b16 {%0,%1,%2,%3}, [%4];"
                 : "=r"(r[0]), "=r"(r[1]), "=r"(r[2]), "=r"(r[3]) : "r"(addr));
}
__device__ __forceinline__ void cp16(uint32_t dst, const void* src) {
    asm volatile("cp.async.cg.shared.global [%0], [%1], 16;" :: "r"(dst), "l"(src));
}
__device__ __forceinline__ void mma_fp16(float* c, const uint32_t* a, const uint32_t* b) {
    asm volatile(
        "mma.sync.aligned.m16n8k16.row.col.f32.f16.f16.f32 "
        "{%0,%1,%2,%3}, {%4,%5,%6,%7}, {%8,%9}, {%0,%1,%2,%3};"
        : "+f"(c[0]), "+f"(c[1]), "+f"(c[2]), "+f"(c[3])
        : "r"(a[0]), "r"(a[1]), "r"(a[2]), "r"(a[3]), "r"(b[0]), "r"(b[1]));
}
__device__ __forceinline__ uint32_t pack2h(float a, float b) {
    const __half2 h = __floats2half2_rn(a, b);
    return *(const uint32_t*)&h;
}

__device__ __forceinline__ int dop_index(int j) {
    if (j == N_DOP - 1) return UNITS - 1;
    const double step = 510.0 / 127.0;
    return (int)((double)j * step + 1.0);
}

// ---------------------------------------------------------------------------
// prep_a: 128 blocks, one per dop neuron (validated R9)
// ---------------------------------------------------------------------------
__global__ void prep_a_kernel(const float* __restrict__ w,
                              const float* __restrict__ dop_old,
                              const float* __restrict__ indicator,
                              const int* __restrict__ bc_raw) {
    __shared__ float red[8];
    const int j = blockIdx.x;
    const int d = dop_index(j);
    const int tid = threadIdx.x, lane = tid & 31, wid = tid >> 5;

    float s = 0.0f;
    for (int i = tid; i < N_INPUT; i += blockDim.x)
        s += fabsf(w[i * UNITS + d] - dop_old[i * UNITS + d]);
    #pragma unroll
    for (int o = 16; o > 0; o >>= 1) s += __shfl_xor_sync(0xffffffffu, s, o);
    if (lane == 0) red[wid] = s;
    __syncthreads();
    if (tid == 0) {
        float t = 0.0f;
        #pragma unroll
        for (int q = 0; q < 8; q++) t += red[q];
        float bc;
        {
            int iv = bc_raw[0];
            if (iv >= -1000000 && iv <= 1000000) bc = (float)iv;
            else bc = __int_as_float(iv);
        }
        const float diff = t * (1.0f / (float)N_INPUT);
        g_fac[j] = 1.0f + 10.0f * diff;
        g_act[j] = (diff > 0.0f) && ((bc - indicator[j]) > 2.0f);
    }
}

// ---------------------------------------------------------------------------
// prep_b: build g_mult (two-phase; R3/R9-validated logic)
// ---------------------------------------------------------------------------
__global__ void prep_b_kernel() {
    __shared__ float s_mult[UNITS];
    __shared__ unsigned char s_isdop[UNITS];
    const int tid = threadIdx.x;
    s_mult[tid] = 1.0f;
    s_isdop[tid] = 0;
    __syncthreads();
    if (tid < N_DOP) s_isdop[dop_index(tid)] = 1;
    __syncthreads();
    if (tid < N_DOP) {
        const int d = dop_index(tid);
        const int c = d - 1;
        if (g_act[tid] && !s_isdop[c]) s_mult[c] *= g_fac[tid];
    }
    __syncthreads();
    if (tid < N_DOP) {
        const int d = dop_index(tid);
        const int c = (d + 1) & (UNITS - 1);
        const bool rightok = (d + 1 >= UNITS) ? true : (!s_isdop[d + 1]);
        if (g_act[tid] && rightok) s_mult[c] *= g_fac[tid];
    }
    __syncthreads();
    g_mult[tid] = s_mult[tid];
}

// ---------------------------------------------------------------------------
// prep2: coalesced transpose+scale+fp16 (validated R9)
// ---------------------------------------------------------------------------
__global__ void prep2_kernel(const float* __restrict__ w) {
    __shared__ float tile[32][33];
    const int tx = threadIdx.x, ty = threadIdx.y;
    const int n0 = blockIdx.x * 32, k0 = blockIdx.y * 32;
    tile[ty][tx] = w[(size_t)(k0 + ty) * UNITS + n0 + tx];
    __syncthreads();
    const float m = g_mult[n0 + ty];
    g_w16[(size_t)(n0 + ty) * N_INPUT + k0 + tx] = __float2half_rn(tile[tx][ty] * m);
}

// ---------------------------------------------------------------------------
// GEMM: 256 threads, 8 warps (4M x 2N), warp tile 32x64, 2 CTAs/SM
// ---------------------------------------------------------------------------
__global__ __launch_bounds__(THREADS, 2)
void gemm_kernel(const float* __restrict__ X, const float* __restrict__ bias,
                 float* __restrict__ C) {
    extern __shared__ char dsm[];
    __shared__ float sbias[BN];

    const int tid = threadIdx.x, lane = tid & 31, wid = tid >> 5;
    const int bx = blockIdx.x, by = blockIdx.y;
    const uint32_t raw = smem_u32(dsm);
    const uint32_t base = (raw + 127u) & ~127u;
    char* smp = dsm + (base - raw);

    if (tid < BN) sbias[tid] = bias[bx * BN + tid];

    const int warp_m = wid & 3;      // 4 warps in M (32 rows each)
    const int warp_n = wid >> 2;     // 2 warps in N (64 cols each)

    // loader: 2 slots of 16B chunks per thread per matrix
    const int r0_ = tid >> 2, c0_ = tid & 3;                 // slot 0: rows 0..63
    const int r1_ = (tid + 256) >> 2, c1_ = c0_;             // slot 1: rows 64..127
    const uint32_t sts0 = swz(r0_, c0_), sts1 = swz(r1_, c1_);
    const float* gA0 = X + ((size_t)by * BM + r0_) * N_INPUT + c0_ * 8;
    const float* gA1 = X + ((size_t)by * BM + r1_) * N_INPUT + c1_ * 8;
    const __half* gB0 = g_w16 + ((size_t)bx * BN + r0_) * N_INPUT + c0_ * 8;
    const __half* gB1 = g_w16 + ((size_t)bx * BN + r1_) * N_INPUT + c1_ * 8;

    float acc[2][8][4];
    #pragma unroll
    for (int mt = 0; mt < 2; mt++)
        #pragma unroll
        for (int nt = 0; nt < 8; nt++)
            #pragma unroll
            for (int q = 0; q < 4; q++) acc[mt][nt][q] = 0.0f;

    // ---- prologue: stage 0 into buffer 0 ----
    {
        cp16(base + OFF_B + sts0, gB0);
        cp16(base + OFF_B + sts1, gB1);
        asm volatile("cp.async.commit_group;" ::: "memory");
        const float4 a00 = *(const float4*)gA0;
        const float4 a01 = *(const float4*)(gA0 + 4);
        const float4 a10 = *(const float4*)gA1;
        const float4 a11 = *(const float4*)(gA1 + 4);
        *(uint4*)(smp + OFF_A + sts0) = make_uint4(
            pack2h(a00.x, a00.y), pack2h(a00.z, a00.w),
            pack2h(a01.x, a01.y), pack2h(a01.z, a01.w));
        *(uint4*)(smp + OFF_A + sts1) = make_uint4(
            pack2h(a10.x, a10.y), pack2h(a10.z, a10.w),
            pack2h(a11.x, a11.y), pack2h(a11.z, a11.w));
        asm volatile("cp.async.wait_group 0;" ::: "memory");
        __syncthreads();
    }

    uint32_t buf = 0;
    for (int s = 0; s < KSTAGES; s++) {
        const uint32_t cb = base + buf;
        const uint32_t nbuf = buf ^ BUF_STRIDE;
        const bool pf = (s + 1 < KSTAGES);
        float4 a00, a01, a10, a11;
        if (pf) {
            const int ko = (s + 1) * BK;
            cp16(base + nbuf + OFF_B + sts0, gB0 + ko);
            cp16(base + nbuf + OFF_B + sts1, gB1 + ko);
            asm volatile("cp.async.commit_group;" ::: "memory");
            a00 = *(const float4*)(gA0 + ko);
            a01 = *(const float4*)(gA0 + ko + 4);
            a10 = *(const float4*)(gA1 + ko);
            a11 = *(const float4*)(gA1 + ko + 4);
        }

        #pragma unroll
        for (int ks = 0; ks < 2; ks++) {
            uint32_t ah[2][4], bh[8][2];
            // A: 2 ldsm4, rows warp_m*32 + mt*16 + (lane&15), k-chunk by lane>>4
            #pragma unroll
            for (int mt = 0; mt < 2; mt++) {
                const int row = warp_m * 32 + mt * 16 + (lane & 15);
                const int ch  = ks * 2 + (lane >> 4);
                ldsm4(ah[mt], cb + OFF_A + swz(row, ch));
            }
            // B: 4 ldsm4, each covers 2 n-tiles x 2 k-halves
            // lane group g=lane>>3: matrix g = (nt_local = g>>1, khalf = g&1)
            #pragma unroll
            for (int np = 0; np < 4; np++) {
                const int g = lane >> 3;
                const int row = warp_n * 64 + (np * 2 + (g >> 1)) * 8 + (lane & 7);
                const int ch  = ks * 2 + (g & 1);
                uint32_t r[4];
                ldsm4(r, cb + OFF_B + swz(row, ch));
                bh[np * 2 + 0][0] = r[0]; bh[np * 2 + 0][1] = r[1];
                bh[np * 2 + 1][0] = r[2]; bh[np * 2 + 1][1] = r[3];
            }
            #pragma unroll
            for (int mt = 0; mt < 2; mt++)
                #pragma unroll
                for (int nt = 0; nt < 8; nt++)
                    mma_fp16(acc[mt][nt], ah[mt], bh[nt]);
        }

        if (pf) {
            *(uint4*)(smp + nbuf + OFF_A + sts0) = make_uint4(
                pack2h(a00.x, a00.y), pack2h(a00.z, a00.w),
                pack2h(a01.x, a01.y), pack2h(a01.z, a01.w));
            *(uint4*)(smp + nbuf + OFF_A + sts1) = make_uint4(
                pack2h(a10.x, a10.y), pack2h(a10.z, a10.w),
                pack2h(a11.x, a11.y), pack2h(a11.z, a11.w));
            asm volatile("cp.async.wait_group 0;" ::: "memory");
        }
        __syncthreads();
        buf = nbuf;
    }

    // ---- epilogue: bias + relu, float2 stores ----
    const int gq = lane >> 2, tq = lane & 3;
    #pragma unroll
    for (int mt = 0; mt < 2; mt++) {
        const int r0 = warp_m * 32 + mt * 16 + gq;
        float* crow0 = C + ((size_t)by * BM + r0) * UNITS + bx * BN;
        float* crow1 = crow0 + 8 * UNITS;
        #pragma unroll
        for (int nt = 0; nt < 8; nt++) {
            const int col = warp_n * 64 + nt * 8 + tq * 2;
            float2 o0, o1;
            o0.x = fmaxf(acc[mt][nt][0] + sbias[col], 0.0f);
            o0.y = fmaxf(acc[mt][nt][1] + sbias[col + 1], 0.0f);
            o1.x = fmaxf(acc[mt][nt][2] + sbias[col], 0.0f);
            o1.y = fmaxf(acc[mt][nt][3] + sbias[col + 1], 0.0f);
            *(float2*)(crow0 + col) = o0;
            *(float2*)(crow1 + col) = o1;
        }
    }
}

extern "C" void kernel_launch(void* const* d_in, const int* in_sizes, int n_in,
                              void* d_out, int out_size) {
    const float* x   = (const float*)d_in[0];
    const float* w   = (const float*)d_in[1];
    const float* b   = (const float*)d_in[2];
    const float* old = (const float*)d_in[3];
    const float* ind = (const float*)d_in[4];
    const int*   bc  = (const int*)d_in[5];

    const int M = in_sizes[0] / N_INPUT;

    cudaFuncSetAttribute(gemm_kernel, cudaFuncAttributeMaxDynamicSharedMemorySize, SMEM_DYN);

    prep_a_kernel<<<N_DOP, 256>>>(w, old, ind, bc);
    prep_b_kernel<<<1, UNITS>>>();
    dim3 tgrid(UNITS / 32, N_INPUT / 32);
    prep2_kernel<<<tgrid, dim3(32, 32)>>>(w);
    dim3 grid(UNITS / BN, M / BM);
    gemm_kernel<<<grid, THREADS, SMEM_DYN>>>(x, b, (float*)d_out);
}